// round 12
// baseline (speedup 1.0000x reference)
#include <cuda_runtime.h>
#include <cuda_bf16.h>
#include <cstdint>

#define NNODE 50000
#define NEDGE 800000
#define DIM   64
#define NREL  65
#define TILE  128
#define EPB   1024
#define NB    ((NEDGE + EPB - 1) / EPB)          // 782
#define NTILES_MAX ((NEDGE + TILE - 1) / TILE + NREL)
#define SAK   72    // smem row stride in bf16 units (144B; conflict-free)
#define SBK   72

// ---- scratch (static device globals; no allocation) ----
__device__ int   g_cnt[NNODE * NREL];
__device__ int   g_blockHist[NB * NREL];
__device__ int   g_relCnt[NREL];
__device__ int   g_relOff[NREL + 1];
__device__ int   g_tileRel[NTILES_MAX];
__device__ int   g_tileStart[NTILES_MAX];
__device__ int   g_numTiles;
__device__ int   g_srcP[NEDGE];
__device__ int   g_dstP[NEDGE];
__device__ float g_normP[NEDGE];
__device__ float g_h[NNODE * DIM];
// pre-split bf16 buffers: row = 128 bf16 (hi[0:64], lo[64:128]) = 256B
__device__ __nv_bfloat16 g_Xs[(size_t)NNODE * 128];
__device__ __nv_bfloat16 g_Hs[(size_t)NNODE * 128];
// W splits: 66 slots (65 relations + self-loop W), [slot][n][128]: hi(k) 0:64, lo(k) 64:128
__device__ __nv_bfloat16 g_Ws1[(size_t)(NREL + 1) * DIM * 128];
__device__ __nv_bfloat16 g_Ws2[(size_t)(NREL + 1) * DIM * 128];

#define MMA_BF16(c, a, b0, b1)                                                   \
    asm volatile("mma.sync.aligned.m16n8k16.row.col.f32.bf16.bf16.f32 "          \
                 "{%0,%1,%2,%3},{%4,%5,%6,%7},{%8,%9},{%0,%1,%2,%3};"            \
                 : "+f"(c[0]), "+f"(c[1]), "+f"(c[2]), "+f"(c[3])                \
                 : "r"(a[0]), "r"(a[1]), "r"(a[2]), "r"(a[3]), "r"(b0), "r"(b1))

#define CP16(dst_u32, src_ptr)                                                   \
    asm volatile("cp.async.cg.shared.global [%0], [%1], 16;"                     \
                 :: "r"(dst_u32), "l"(src_ptr))
#define CP_COMMIT() asm volatile("cp.async.commit_group;")
#define CP_WAIT0()  asm volatile("cp.async.wait_group 0;")

#define RED4(ptr, a, b, c, d)                                                    \
    asm volatile("red.global.add.v4.f32 [%0], {%1,%2,%3,%4};"                    \
                 :: "l"(ptr), "f"(a), "f"(b), "f"(c), "f"(d) : "memory")

__device__ __forceinline__ uint32_t smem_u32(const void* p) {
    uint32_t a;
    asm("{ .reg .u64 t; cvta.to.shared.u64 t, %1; cvt.u32.u64 %0, t; }"
        : "=r"(a) : "l"(p));
    return a;
}

// SMEM layout (bytes)
#define SM_DST  0
#define SM_NRM  512
#define SM_AH   1024
#define ASZ     (TILE * SAK * 2)                 // 18432
#define SM_AL   (SM_AH + ASZ + 16)               // 19472
#define SM_BH   (SM_AL + ASZ + 16)               // 37920
#define BSZ     (DIM * SBK * 2)                  // 9216
#define SM_BL   (SM_BH + BSZ + 16)               // 47152
#define SM_TOT  (SM_BL + BSZ)                    // 56368

// ---------------------------------------------------------------- histogram (warp-aggregated)
__global__ void __launch_bounds__(256) k_hist(const int* __restrict__ dst,
                                              const int* __restrict__ et) {
    __shared__ int h[NREL];
    int tid = threadIdx.x, b = blockIdx.x;
    int lane = tid & 31;
    if (tid < NREL) h[tid] = 0;
    __syncthreads();
    int s = b * EPB, e_end = min(s + EPB, NEDGE);
    // trip counts are warp-uniform (EPB and NEDGE multiples of 256)
    for (int e = s + tid; e < e_end; e += 256) {
        int r = et[e];
        unsigned peers = __match_any_sync(0xffffffffu, r);
        int leader = __ffs(peers) - 1;
        if (lane == leader) atomicAdd(&h[r], __popc(peers));
        atomicAdd(&g_cnt[dst[e] * NREL + r], 1);   // spread: 3.25M addresses
    }
    __syncthreads();
    if (tid < NREL) g_blockHist[b * NREL + tid] = h[tid];
}

// ---------------------------------------------------------------- per-relation block scan (parallel)
__global__ void __launch_bounds__(128) k_scanRel() {
    __shared__ int ts[128];
    int r = blockIdx.x, t = threadIdx.x;
    int base = t * 8;
    int v[8];
#pragma unroll
    for (int i = 0; i < 8; i++)
        v[i] = (base + i < NB) ? g_blockHist[(base + i) * NREL + r] : 0;
    int sum = 0;
#pragma unroll
    for (int i = 0; i < 8; i++) sum += v[i];
    ts[t] = sum;
    __syncthreads();
    for (int off = 1; off < 128; off <<= 1) {
        int add = (t >= off) ? ts[t - off] : 0;
        __syncthreads();
        ts[t] += add;
        __syncthreads();
    }
    if (t == 127) g_relCnt[r] = ts[127];
    int run = ts[t] - sum;
#pragma unroll
    for (int i = 0; i < 8; i++) {
        if (base + i < NB) {
            int tmp = v[i];
            g_blockHist[(base + i) * NREL + r] = run;
            run += tmp;
        }
    }
}

// ---------------------------------------------------------------- relation offsets + fused tile table
__global__ void k_scanTiles() {
    __shared__ int a[128], b2[128];
    __shared__ int relOffS[NREL + 1], tileBaseS[NREL + 1];
    int t = threadIdx.x;
    int c  = (t < NREL) ? g_relCnt[t] : 0;
    int nt = (c + TILE - 1) / TILE;
    a[t] = c; b2[t] = nt;
    __syncthreads();
    for (int off = 1; off < 128; off <<= 1) {
        int av = a[t], bv = b2[t];
        int au = (t >= off) ? a[t - off] : 0;
        int bu = (t >= off) ? b2[t - off] : 0;
        __syncthreads();
        a[t] = av + au; b2[t] = bv + bu;
        __syncthreads();
    }
    if (t < NREL) {
        g_relOff[t]  = a[t] - c;
        relOffS[t]   = a[t] - c;
        tileBaseS[t] = b2[t] - nt;
    }
    if (t == NREL - 1) {
        g_relOff[NREL]  = a[t];
        relOffS[NREL]   = a[t];
        tileBaseS[NREL] = b2[t];
        g_numTiles      = b2[t];
    }
    __syncthreads();
    int total = tileBaseS[NREL];
    for (int tt = t; tt < total; tt += 128) {
        int lo = 0, hi = NREL;
        while (lo + 1 < hi) {
            int mid = (lo + hi) >> 1;
            if (tileBaseS[mid] <= tt) lo = mid; else hi = mid;
        }
        g_tileRel[tt]   = lo;
        g_tileStart[tt] = relOffS[lo] + (tt - tileBaseS[lo]) * TILE;
    }
}

// ---------------------------------------------------------------- scatter sorted arrays (warp-aggregated rank)
__global__ void __launch_bounds__(256) k_scatter(const int* __restrict__ src,
                                                 const int* __restrict__ dst,
                                                 const int* __restrict__ et) {
    __shared__ int cur[NREL];
    int tid = threadIdx.x, b = blockIdx.x;
    int lane = tid & 31;
    if (tid < NREL) cur[tid] = g_relOff[tid] + g_blockHist[b * NREL + tid];
    __syncthreads();
    int s = b * EPB, e_end = min(s + EPB, NEDGE);
    for (int e = s + tid; e < e_end; e += 256) {
        int r = et[e], d = dst[e];
        unsigned peers = __match_any_sync(0xffffffffu, r);
        int leader = __ffs(peers) - 1;
        int rank = __popc(peers & ((1u << lane) - 1u));
        int base;
        if (lane == leader) base = atomicAdd(&cur[r], __popc(peers));
        base = __shfl_sync(0xffffffffu, base, leader);
        int pos = base + rank;
        g_srcP[pos]  = src[e];
        g_dstP[pos]  = d;
        g_normP[pos] = 1.0f / (float)max(g_cnt[d * NREL + r], 1);
    }
}

// ---------------------------------------------------------------- W split (both layers in one launch)
__global__ void __launch_bounds__(256) k_wsplit(const float* __restrict__ W1,
                                                const float* __restrict__ Wl1,
                                                const float* __restrict__ W2,
                                                const float* __restrict__ Wl2,
                                                __nv_bfloat16* __restrict__ o1,
                                                __nv_bfloat16* __restrict__ o2) {
    int rb = blockIdx.x;
    int layer = rb >= (NREL + 1);
    int r = layer ? rb - (NREL + 1) : rb;
    const float* W  = layer ? W2 : W1;
    const float* Wl = layer ? Wl2 : Wl1;
    __nv_bfloat16* out = layer ? o2 : o1;
    const float* src = (r < NREL) ? (W + (size_t)r * DIM * DIM) : Wl;
    int t = threadIdx.x;
    int n = t >> 2, kc = (t & 3) * 16;
    __nv_bfloat16 h[16], l[16];
#pragma unroll
    for (int kk = 0; kk < 16; kk++) {
        float v = src[(kc + kk) * DIM + n];
        __nv_bfloat16 hh = __float2bfloat16_rn(v);
        h[kk] = hh;
        l[kk] = __float2bfloat16_rn(v - __bfloat162float(hh));
    }
    __nv_bfloat16* o = out + ((size_t)(r * DIM + n) * 128 + kc);
    *(uint4*)o        = *(uint4*)&h[0];
    *(uint4*)(o + 8)  = *(uint4*)&h[8];
    *(uint4*)(o + 64) = *(uint4*)&l[0];
    *(uint4*)(o + 72) = *(uint4*)&l[8];
}

// ---------------------------------------------------------------- X split
__global__ void k_xsplit(const float* __restrict__ X, __nv_bfloat16* __restrict__ Xs) {
    int i = blockIdx.x * blockDim.x + threadIdx.x;
    if (i >= NNODE * 8) return;
    int row = i >> 3, seg = i & 7;
    const float4* p = (const float4*)(X + (size_t)row * DIM + seg * 8);
    float4 v0 = p[0], v1 = p[1];
    float vv[8] = {v0.x, v0.y, v0.z, v0.w, v1.x, v1.y, v1.z, v1.w};
    __nv_bfloat16 h[8], l[8];
#pragma unroll
    for (int j = 0; j < 8; j++) {
        __nv_bfloat16 hh = __float2bfloat16_rn(vv[j]);
        h[j] = hh;
        l[j] = __float2bfloat16_rn(vv[j] - __bfloat162float(hh));
    }
    __nv_bfloat16* o = Xs + (size_t)row * 128 + seg * 8;
    *(uint4*)o        = *(uint4*)h;
    *(uint4*)(o + 64) = *(uint4*)l;
}

// ---------------------------------------------------------------- relu + split (layer boundary)
__global__ void k_relu_split(const float* __restrict__ O, __nv_bfloat16* __restrict__ Xs) {
    int i = blockIdx.x * blockDim.x + threadIdx.x;
    if (i >= NNODE * 8) return;
    int row = i >> 3, seg = i & 7;
    const float4* p = (const float4*)(O + (size_t)row * DIM + seg * 8);
    float4 v0 = p[0], v1 = p[1];
    float vv[8] = {fmaxf(v0.x, 0.f), fmaxf(v0.y, 0.f), fmaxf(v0.z, 0.f), fmaxf(v0.w, 0.f),
                   fmaxf(v1.x, 0.f), fmaxf(v1.y, 0.f), fmaxf(v1.z, 0.f), fmaxf(v1.w, 0.f)};
    __nv_bfloat16 h[8], l[8];
#pragma unroll
    for (int j = 0; j < 8; j++) {
        __nv_bfloat16 hh = __float2bfloat16_rn(vv[j]);
        h[j] = hh;
        l[j] = __float2bfloat16_rn(vv[j] - __bfloat162float(hh));
    }
    __nv_bfloat16* o = Xs + (size_t)row * 128 + seg * 8;
    *(uint4*)o        = *(uint4*)h;
    *(uint4*)(o + 64) = *(uint4*)l;
}

// ---------------------------------------------------------------- edge kernel (cp.async gather)
__global__ void __launch_bounds__(256, 3) k_edges(const __nv_bfloat16* __restrict__ Xs,
                                                  const __nv_bfloat16* __restrict__ Ws,
                                                  float* __restrict__ O) {
    int t = blockIdx.x;
    if (t >= g_numTiles) return;
    int r  = g_tileRel[t];
    int s0 = g_tileStart[t];
    int m  = min(g_relOff[r + 1] - s0, TILE);

    extern __shared__ char smem[];
    uint32_t sb = smem_u32(smem);
    int*   sDst  = (int*)(smem + SM_DST);
    float* sNorm = (float*)(smem + SM_NRM);
    int tid = threadIdx.x;

    // ---- B tile via cp.async (4 x 16B per thread) ----
    {
        int n = tid >> 2, c = tid & 3;
        const char* wr = (const char*)(Ws + ((size_t)(r * DIM + n) * 128 + (c & 1) * 32 + (c >> 1) * 64));
        uint32_t db = sb + ((c >> 1) ? SM_BL : SM_BH) + n * 144 + (c & 1) * 64;
#pragma unroll
        for (int j = 0; j < 4; j++) CP16(db + j * 16, wr + j * 16);
    }
    // ---- A gather via cp.async (2 threads per row, 8 x 16B each) ----
    {
        int e = tid >> 1, half = tid & 1;
        uint32_t ah = sb + SM_AH + e * 144 + half * 64;
        uint32_t al = sb + SM_AL + e * 144 + half * 64;
        if (e < m) {
            int sr = g_srcP[s0 + e];
            if (half == 0) { sDst[e] = g_dstP[s0 + e]; sNorm[e] = g_normP[s0 + e]; }
            const char* xr = (const char*)(Xs + (size_t)sr * 128) + half * 64;
#pragma unroll
            for (int j = 0; j < 4; j++) CP16(ah + j * 16, xr + j * 16);
#pragma unroll
            for (int j = 0; j < 4; j++) CP16(al + j * 16, xr + 128 + j * 16);
        } else {
            uint4 z = make_uint4(0, 0, 0, 0);
#pragma unroll
            for (int j = 0; j < 4; j++) {
                *(uint4*)(smem + SM_AH + e * 144 + half * 64 + j * 16) = z;
                *(uint4*)(smem + SM_AL + e * 144 + half * 64 + j * 16) = z;
            }
        }
    }
    CP_COMMIT();
    CP_WAIT0();
    __syncthreads();

    int lane = tid & 31, wid = tid >> 5;
    int g = lane >> 2, tg = lane & 3;
    int m0 = wid * 16;

    float c[8][4];
#pragma unroll
    for (int n = 0; n < 8; n++) { c[n][0] = 0.f; c[n][1] = 0.f; c[n][2] = 0.f; c[n][3] = 0.f; }

#pragma unroll
    for (int ks = 0; ks < 4; ks++) {
        int k0 = ks * 16;
        uint32_t ah[4], al[4];
        {
            const char* pLo = smem + SM_AH + ((m0 + g) * SAK + k0 + 2 * tg) * 2;
            const char* pHi = pLo + 8 * SAK * 2;
            ah[0] = *(const uint32_t*)pLo;  ah[1] = *(const uint32_t*)pHi;
            ah[2] = *(const uint32_t*)(pLo + 16); ah[3] = *(const uint32_t*)(pHi + 16);
            const char* qLo = smem + SM_AL + ((m0 + g) * SAK + k0 + 2 * tg) * 2;
            const char* qHi = qLo + 8 * SAK * 2;
            al[0] = *(const uint32_t*)qLo;  al[1] = *(const uint32_t*)qHi;
            al[2] = *(const uint32_t*)(qLo + 16); al[3] = *(const uint32_t*)(qHi + 16);
        }
#pragma unroll
        for (int n = 0; n < 8; n++) {
            uint32_t off = (uint32_t)((n * 8 + g) * SBK + k0 + 2 * tg) * 2;
            uint32_t bh0 = *(const uint32_t*)(smem + SM_BH + off);
            uint32_t bh1 = *(const uint32_t*)(smem + SM_BH + off + 16);
            uint32_t bl0 = *(const uint32_t*)(smem + SM_BL + off);
            uint32_t bl1 = *(const uint32_t*)(smem + SM_BL + off + 16);
            MMA_BF16(c[n], ah, bh0, bh1);
            MMA_BF16(c[n], al, bh0, bh1);
            MMA_BF16(c[n], ah, bl0, bl1);
        }
    }

    // epilogue: norm, shfl-pair, red.global.add.v4
    int  col0 = (tg & 2) * 2;
    bool lead = (tg & 1) == 0;
    int rA = m0 + g, rB = rA + 8;
    int dA = (rA < m) ? sDst[rA] : -1;
    int dB = (rB < m) ? sDst[rB] : -1;
    float nA = (rA < m) ? sNorm[rA] : 0.f;
    float nB = (rB < m) ? sNorm[rB] : 0.f;
#pragma unroll
    for (int n = 0; n < 8; n++) {
        float x0 = c[n][0] * nA, y0 = c[n][1] * nA;
        float x1 = c[n][2] * nB, y1 = c[n][3] * nB;
        float qx0 = __shfl_xor_sync(0xffffffffu, x0, 1);
        float qy0 = __shfl_xor_sync(0xffffffffu, y0, 1);
        float qx1 = __shfl_xor_sync(0xffffffffu, x1, 1);
        float qy1 = __shfl_xor_sync(0xffffffffu, y1, 1);
        if (lead && dA >= 0)
            RED4(O + (size_t)dA * DIM + n * 8 + col0, x0, y0, qx0, qy0);
        if (lead && dB >= 0)
            RED4(O + (size_t)dB * DIM + n * 8 + col0, x1, y1, qx1, qy1);
    }
}

// ---------------------------------------------------------------- self-loop: O += X @ Wl (red.add; O pre-zeroed)
__global__ void __launch_bounds__(256, 3) k_selfloop(const __nv_bfloat16* __restrict__ Xs,
                                                     const __nv_bfloat16* __restrict__ Ws,
                                                     float* __restrict__ O) {
    int base = blockIdx.x * TILE;
    int m = min(TILE, NNODE - base);
    extern __shared__ char smem[];
    uint32_t sb = smem_u32(smem);
    int tid = threadIdx.x;

    {
        int n = tid >> 2, c = tid & 3;
        const char* wr = (const char*)(Ws + ((size_t)(NREL * DIM + n) * 128 + (c & 1) * 32 + (c >> 1) * 64));
        uint32_t db = sb + ((c >> 1) ? SM_BL : SM_BH) + n * 144 + (c & 1) * 64;
#pragma unroll
        for (int j = 0; j < 4; j++) CP16(db + j * 16, wr + j * 16);
    }
    {
        int e = tid >> 1, half = tid & 1;
        uint32_t ah = sb + SM_AH + e * 144 + half * 64;
        uint32_t al = sb + SM_AL + e * 144 + half * 64;
        if (e < m) {
            const char* xr = (const char*)(Xs + (size_t)(base + e) * 128) + half * 64;
#pragma unroll
            for (int j = 0; j < 4; j++) CP16(ah + j * 16, xr + j * 16);
#pragma unroll
            for (int j = 0; j < 4; j++) CP16(al + j * 16, xr + 128 + j * 16);
        } else {
            uint4 z = make_uint4(0, 0, 0, 0);
#pragma unroll
            for (int j = 0; j < 4; j++) {
                *(uint4*)(smem + SM_AH + e * 144 + half * 64 + j * 16) = z;
                *(uint4*)(smem + SM_AL + e * 144 + half * 64 + j * 16) = z;
            }
        }
    }
    CP_COMMIT();
    CP_WAIT0();
    __syncthreads();

    int lane = tid & 31, wid = tid >> 5;
    int g = lane >> 2, tg = lane & 3;
    int m0 = wid * 16;

    float c[8][4];
#pragma unroll
    for (int n = 0; n < 8; n++) { c[n][0] = 0.f; c[n][1] = 0.f; c[n][2] = 0.f; c[n][3] = 0.f; }

#pragma unroll
    for (int ks = 0; ks < 4; ks++) {
        int k0 = ks * 16;
        uint32_t ah[4], al[4];
        {
            const char* pLo = smem + SM_AH + ((m0 + g) * SAK + k0 + 2 * tg) * 2;
            const char* pHi = pLo + 8 * SAK * 2;
            ah[0] = *(const uint32_t*)pLo;  ah[1] = *(const uint32_t*)pHi;
            ah[2] = *(const uint32_t*)(pLo + 16); ah[3] = *(const uint32_t*)(pHi + 16);
            const char* qLo = smem + SM_AL + ((m0 + g) * SAK + k0 + 2 * tg) * 2;
            const char* qHi = qLo + 8 * SAK * 2;
            al[0] = *(const uint32_t*)qLo;  al[1] = *(const uint32_t*)qHi;
            al[2] = *(const uint32_t*)(qLo + 16); al[3] = *(const uint32_t*)(qHi + 16);
        }
#pragma unroll
        for (int n = 0; n < 8; n++) {
            uint32_t off = (uint32_t)((n * 8 + g) * SBK + k0 + 2 * tg) * 2;
            uint32_t bh0 = *(const uint32_t*)(smem + SM_BH + off);
            uint32_t bh1 = *(const uint32_t*)(smem + SM_BH + off + 16);
            uint32_t bl0 = *(const uint32_t*)(smem + SM_BL + off);
            uint32_t bl1 = *(const uint32_t*)(smem + SM_BL + off + 16);
            MMA_BF16(c[n], ah, bh0, bh1);
            MMA_BF16(c[n], al, bh0, bh1);
            MMA_BF16(c[n], ah, bl0, bl1);
        }
    }

    int  col0 = (tg & 2) * 2;
    bool lead = (tg & 1) == 0;
    int rA = m0 + g, rB = rA + 8;
    bool okA = rA < m, okB = rB < m;
#pragma unroll
    for (int n = 0; n < 8; n++) {
        float x0 = c[n][0], y0 = c[n][1];
        float x1 = c[n][2], y1 = c[n][3];
        float qx0 = __shfl_xor_sync(0xffffffffu, x0, 1);
        float qy0 = __shfl_xor_sync(0xffffffffu, y0, 1);
        float qx1 = __shfl_xor_sync(0xffffffffu, x1, 1);
        float qy1 = __shfl_xor_sync(0xffffffffu, y1, 1);
        if (lead && okA)
            RED4(O + (size_t)(base + rA) * DIM + n * 8 + col0, x0, y0, qx0, qy0);
        if (lead && okB)
            RED4(O + (size_t)(base + rB) * DIM + n * 8 + col0, x1, y1, qx1, qy1);
    }
}

// ---------------------------------------------------------------- relu (final)
__global__ void k_relu(float* __restrict__ O, int n4) {
    int i = blockIdx.x * blockDim.x + threadIdx.x;
    if (i < n4) {
        float4 v = ((float4*)O)[i];
        v.x = fmaxf(v.x, 0.f); v.y = fmaxf(v.y, 0.f);
        v.z = fmaxf(v.z, 0.f); v.w = fmaxf(v.w, 0.f);
        ((float4*)O)[i] = v;
    }
}

// ---------------------------------------------------------------- launch
extern "C" void kernel_launch(void* const* d_in, const int* in_sizes, int n_in,
                              void* d_out, int out_size) {
    const float* x   = (const float*)d_in[0];
    const int*   src = (const int*)d_in[1];
    const int*   dst = (const int*)d_in[2];
    const int*   et  = (const int*)d_in[3];
    const float* W1  = (const float*)d_in[4];
    const float* Wl1 = (const float*)d_in[5];
    const float* W2  = (const float*)d_in[6];
    const float* Wl2 = (const float*)d_in[7];
    float* out = (float*)d_out;

    void* p;
    cudaGetSymbolAddress(&p, g_h);   float* h  = (float*)p;
    cudaGetSymbolAddress(&p, g_Xs);  __nv_bfloat16* Xs = (__nv_bfloat16*)p;
    cudaGetSymbolAddress(&p, g_Hs);  __nv_bfloat16* Hs = (__nv_bfloat16*)p;
    cudaGetSymbolAddress(&p, g_Ws1); __nv_bfloat16* Ws1 = (__nv_bfloat16*)p;
    cudaGetSymbolAddress(&p, g_Ws2); __nv_bfloat16* Ws2 = (__nv_bfloat16*)p;
    void* cntp;
    cudaGetSymbolAddress(&cntp, g_cnt);

    cudaFuncSetAttribute(k_edges,    cudaFuncAttributeMaxDynamicSharedMemorySize, SM_TOT);
    cudaFuncSetAttribute(k_selfloop, cudaFuncAttributeMaxDynamicSharedMemorySize, SM_TOT);

    const int TPB = 256;
    int nBlocksRows = (NNODE + TILE - 1) / TILE;
    int n4 = NNODE * DIM / 4;

    cudaStream_t s1;
    cudaStreamCreateWithFlags(&s1, cudaStreamNonBlocking);
    cudaEvent_t e0, e_xs, e_sl1, e_rs, e_sl2;
    cudaEventCreateWithFlags(&e0,   cudaEventDisableTiming);
    cudaEventCreateWithFlags(&e_xs, cudaEventDisableTiming);
    cudaEventCreateWithFlags(&e_sl1, cudaEventDisableTiming);
    cudaEventCreateWithFlags(&e_rs,  cudaEventDisableTiming);
    cudaEventCreateWithFlags(&e_sl2, cudaEventDisableTiming);

    // only the cnt memset gates branch A; fork immediately
    cudaMemsetAsync(cntp, 0, (size_t)NNODE * NREL * sizeof(int));
    cudaEventRecord(e0, 0);
    cudaStreamWaitEvent(s1, e0, 0);

    // branch A (main): counting-sort preprocessing
    k_hist<<<NB, TPB>>>(dst, et);
    k_scanRel<<<NREL, 128>>>();
    k_scanTiles<<<1, 128>>>();
    k_scatter<<<NB, TPB>>>(src, dst, et);

    // branch B (side): output zeroing + splits + layer-1 self-loop (red into h)
    cudaMemsetAsync(h,   0, (size_t)NNODE * DIM * sizeof(float), s1);
    cudaMemsetAsync(out, 0, (size_t)NNODE * DIM * sizeof(float), s1);
    k_wsplit<<<2 * (NREL + 1), 256, 0, s1>>>(W1, Wl1, W2, Wl2, Ws1, Ws2);
    k_xsplit<<<(NNODE * 8 + 255) / 256, 256, 0, s1>>>(x, Xs);
    cudaEventRecord(e_xs, s1);
    k_selfloop<<<nBlocksRows, TPB, SM_TOT, s1>>>(Xs, Ws1, h);
    cudaEventRecord(e_sl1, s1);

    // edges1 needs sort (main order) + Xs + zeroed h (e_xs); NOT selfloop1
    cudaStreamWaitEvent(0, e_xs, 0);
    k_edges<<<NTILES_MAX, TPB, SM_TOT>>>(Xs, Ws1, h);

    // relu_split needs edges1 (main) + selfloop1 (side)
    cudaStreamWaitEvent(0, e_sl1, 0);
    k_relu_split<<<(NNODE * 8 + 255) / 256, 256>>>(h, Hs);

    // layer 2: selfloop (side) and edges (main) reduce concurrently into zeroed out
    cudaEventRecord(e_rs, 0);
    cudaStreamWaitEvent(s1, e_rs, 0);
    k_selfloop<<<nBlocksRows, TPB, SM_TOT, s1>>>(Hs, Ws2, out);
    cudaEventRecord(e_sl2, s1);
    k_edges<<<NTILES_MAX, TPB, SM_TOT>>>(Hs, Ws2, out);
    cudaStreamWaitEvent(0, e_sl2, 0);

    k_relu<<<(n4 + TPB - 1) / TPB, TPB>>>(out, n4);

    cudaEventDestroy(e0);
    cudaEventDestroy(e_xs);
    cudaEventDestroy(e_sl1);
    cudaEventDestroy(e_rs);
    cudaEventDestroy(e_sl2);
    cudaStreamDestroy(s1);
}

// round 13
// speedup vs baseline: 1.0444x; 1.0444x over previous
#include <cuda_runtime.h>
#include <cuda_bf16.h>
#include <cstdint>

#define NNODE 50000
#define NEDGE 800000
#define DIM   64
#define NREL  65
#define TILE  128
#define EPB   2048
#define NB    ((NEDGE + EPB - 1) / EPB)          // 391
#define NTILES_MAX ((NEDGE + TILE - 1) / TILE + NREL)
#define SAK   72    // smem row stride in bf16 units (144B; conflict-free)
#define SBK   72

// ---- scratch (static device globals; no allocation) ----
__device__ int   g_cnt[NNODE * NREL];
__device__ int   g_blockHist[NB * NREL];
__device__ int   g_relCnt[NREL];
__device__ int   g_relOff[NREL + 1];
__device__ int   g_tileRel[NTILES_MAX];
__device__ int   g_tileStart[NTILES_MAX];
__device__ int   g_numTiles;
__device__ int4  g_edgeP[NEDGE];                 // packed {src, dst, norm_bits, pad}
__device__ float g_h[NNODE * DIM];
// pre-split bf16 buffers: row = 128 bf16 (hi[0:64], lo[64:128]) = 256B
__device__ __nv_bfloat16 g_Xs[(size_t)NNODE * 128];
__device__ __nv_bfloat16 g_Hs[(size_t)NNODE * 128];
// W splits: 66 slots (65 relations + self-loop W), [slot][n][128]: hi(k) 0:64, lo(k) 64:128
__device__ __nv_bfloat16 g_Ws1[(size_t)(NREL + 1) * DIM * 128];
__device__ __nv_bfloat16 g_Ws2[(size_t)(NREL + 1) * DIM * 128];

#define MMA_BF16(c, a, b0, b1)                                                   \
    asm volatile("mma.sync.aligned.m16n8k16.row.col.f32.bf16.bf16.f32 "          \
                 "{%0,%1,%2,%3},{%4,%5,%6,%7},{%8,%9},{%0,%1,%2,%3};"            \
                 : "+f"(c[0]), "+f"(c[1]), "+f"(c[2]), "+f"(c[3])                \
                 : "r"(a[0]), "r"(a[1]), "r"(a[2]), "r"(a[3]), "r"(b0), "r"(b1))

#define CP16(dst_u32, src_ptr)                                                   \
    asm volatile("cp.async.cg.shared.global [%0], [%1], 16;"                     \
                 :: "r"(dst_u32), "l"(src_ptr))
#define CP_COMMIT() asm volatile("cp.async.commit_group;")
#define CP_WAIT0()  asm volatile("cp.async.wait_group 0;")

#define RED4(ptr, a, b, c, d)                                                    \
    asm volatile("red.global.add.v4.f32 [%0], {%1,%2,%3,%4};"                    \
                 :: "l"(ptr), "f"(a), "f"(b), "f"(c), "f"(d) : "memory")

__device__ __forceinline__ uint32_t smem_u32(const void* p) {
    uint32_t a;
    asm("{ .reg .u64 t; cvta.to.shared.u64 t, %1; cvt.u32.u64 %0, t; }"
        : "=r"(a) : "l"(p));
    return a;
}

// SMEM layout (bytes)
#define SM_DST  0
#define SM_NRM  512
#define SM_AH   1024
#define ASZ     (TILE * SAK * 2)                 // 18432
#define SM_AL   (SM_AH + ASZ + 16)               // 19472
#define SM_BH   (SM_AL + ASZ + 16)               // 37920
#define BSZ     (DIM * SBK * 2)                  // 9216
#define SM_BL   (SM_BH + BSZ + 16)               // 47152
#define SM_TOT  (SM_BL + BSZ)                    // 56368

// ---------------------------------------------------------------- histogram
__global__ void __launch_bounds__(256) k_hist(const int* __restrict__ dst,
                                              const int* __restrict__ et) {
    __shared__ int h[NREL];
    int tid = threadIdx.x, b = blockIdx.x;
    if (tid < NREL) h[tid] = 0;
    __syncthreads();
    int s = b * EPB, e_end = min(s + EPB, NEDGE);
    for (int e = s + tid; e < e_end; e += 256) {
        int r = et[e];
        atomicAdd(&h[r], 1);
        atomicAdd(&g_cnt[dst[e] * NREL + r], 1);
    }
    __syncthreads();
    if (tid < NREL) g_blockHist[b * NREL + tid] = h[tid];
}

// ---------------------------------------------------------------- per-relation block scan (parallel)
__global__ void __launch_bounds__(128) k_scanRel() {
    __shared__ int ts[128];
    int r = blockIdx.x, t = threadIdx.x;
    int base = t * 4;
    int v[4];
#pragma unroll
    for (int i = 0; i < 4; i++)
        v[i] = (base + i < NB) ? g_blockHist[(base + i) * NREL + r] : 0;
    int sum = v[0] + v[1] + v[2] + v[3];
    ts[t] = sum;
    __syncthreads();
    for (int off = 1; off < 128; off <<= 1) {
        int add = (t >= off) ? ts[t - off] : 0;
        __syncthreads();
        ts[t] += add;
        __syncthreads();
    }
    if (t == 127) g_relCnt[r] = ts[127];
    int run = ts[t] - sum;
#pragma unroll
    for (int i = 0; i < 4; i++) {
        if (base + i < NB) {
            int tmp = v[i];
            g_blockHist[(base + i) * NREL + r] = run;
            run += tmp;
        }
    }
}

// ---------------------------------------------------------------- relation offsets + fused tile table
__global__ void k_scanTiles() {
    __shared__ int a[128], b2[128];
    __shared__ int relOffS[NREL + 1], tileBaseS[NREL + 1];
    int t = threadIdx.x;
    int c  = (t < NREL) ? g_relCnt[t] : 0;
    int nt = (c + TILE - 1) / TILE;
    a[t] = c; b2[t] = nt;
    __syncthreads();
    for (int off = 1; off < 128; off <<= 1) {
        int av = a[t], bv = b2[t];
        int au = (t >= off) ? a[t - off] : 0;
        int bu = (t >= off) ? b2[t - off] : 0;
        __syncthreads();
        a[t] = av + au; b2[t] = bv + bu;
        __syncthreads();
    }
    if (t < NREL) {
        g_relOff[t]  = a[t] - c;
        relOffS[t]   = a[t] - c;
        tileBaseS[t] = b2[t] - nt;
    }
    if (t == NREL - 1) {
        g_relOff[NREL]  = a[t];
        relOffS[NREL]   = a[t];
        tileBaseS[NREL] = b2[t];
        g_numTiles      = b2[t];
    }
    __syncthreads();
    int total = tileBaseS[NREL];
    for (int tt = t; tt < total; tt += 128) {
        int lo = 0, hi = NREL;
        while (lo + 1 < hi) {
            int mid = (lo + hi) >> 1;
            if (tileBaseS[mid] <= tt) lo = mid; else hi = mid;
        }
        g_tileRel[tt]   = lo;
        g_tileStart[tt] = relOffS[lo] + (tt - tileBaseS[lo]) * TILE;
    }
}

// ---------------------------------------------------------------- scatter sorted packed records
__global__ void __launch_bounds__(256) k_scatter(const int* __restrict__ src,
                                                 const int* __restrict__ dst,
                                                 const int* __restrict__ et) {
    __shared__ int cur[NREL];
    int tid = threadIdx.x, b = blockIdx.x;
    if (tid < NREL) cur[tid] = g_relOff[tid] + g_blockHist[b * NREL + tid];
    __syncthreads();
    int s = b * EPB, e_end = min(s + EPB, NEDGE);
    for (int e = s + tid; e < e_end; e += 256) {
        int r = et[e], d = dst[e];
        int pos = atomicAdd(&cur[r], 1);
        float nrm = 1.0f / (float)max(g_cnt[d * NREL + r], 1);
        g_edgeP[pos] = make_int4(src[e], d, __float_as_int(nrm), 0);
    }
}

// ---------------------------------------------------------------- W split (both layers in one launch)
__global__ void __launch_bounds__(256) k_wsplit(const float* __restrict__ W1,
                                                const float* __restrict__ Wl1,
                                                const float* __restrict__ W2,
                                                const float* __restrict__ Wl2,
                                                __nv_bfloat16* __restrict__ o1,
                                                __nv_bfloat16* __restrict__ o2) {
    int rb = blockIdx.x;
    int layer = rb >= (NREL + 1);
    int r = layer ? rb - (NREL + 1) : rb;
    const float* W  = layer ? W2 : W1;
    const float* Wl = layer ? Wl2 : Wl1;
    __nv_bfloat16* out = layer ? o2 : o1;
    const float* src = (r < NREL) ? (W + (size_t)r * DIM * DIM) : Wl;
    int t = threadIdx.x;
    int n = t >> 2, kc = (t & 3) * 16;
    __nv_bfloat16 h[16], l[16];
#pragma unroll
    for (int kk = 0; kk < 16; kk++) {
        float v = src[(kc + kk) * DIM + n];
        __nv_bfloat16 hh = __float2bfloat16_rn(v);
        h[kk] = hh;
        l[kk] = __float2bfloat16_rn(v - __bfloat162float(hh));
    }
    __nv_bfloat16* o = out + ((size_t)(r * DIM + n) * 128 + kc);
    *(uint4*)o        = *(uint4*)&h[0];
    *(uint4*)(o + 8)  = *(uint4*)&h[8];
    *(uint4*)(o + 64) = *(uint4*)&l[0];
    *(uint4*)(o + 72) = *(uint4*)&l[8];
}

// ---------------------------------------------------------------- X split
__global__ void k_xsplit(const float* __restrict__ X, __nv_bfloat16* __restrict__ Xs) {
    int i = blockIdx.x * blockDim.x + threadIdx.x;
    if (i >= NNODE * 8) return;
    int row = i >> 3, seg = i & 7;
    const float4* p = (const float4*)(X + (size_t)row * DIM + seg * 8);
    float4 v0 = p[0], v1 = p[1];
    float vv[8] = {v0.x, v0.y, v0.z, v0.w, v1.x, v1.y, v1.z, v1.w};
    __nv_bfloat16 h[8], l[8];
#pragma unroll
    for (int j = 0; j < 8; j++) {
        __nv_bfloat16 hh = __float2bfloat16_rn(vv[j]);
        h[j] = hh;
        l[j] = __float2bfloat16_rn(vv[j] - __bfloat162float(hh));
    }
    __nv_bfloat16* o = Xs + (size_t)row * 128 + seg * 8;
    *(uint4*)o        = *(uint4*)h;
    *(uint4*)(o + 64) = *(uint4*)l;
}

// ---------------------------------------------------------------- relu + split (layer boundary)
__global__ void k_relu_split(const float* __restrict__ O, __nv_bfloat16* __restrict__ Xs) {
    int i = blockIdx.x * blockDim.x + threadIdx.x;
    if (i >= NNODE * 8) return;
    int row = i >> 3, seg = i & 7;
    const float4* p = (const float4*)(O + (size_t)row * DIM + seg * 8);
    float4 v0 = p[0], v1 = p[1];
    float vv[8] = {fmaxf(v0.x, 0.f), fmaxf(v0.y, 0.f), fmaxf(v0.z, 0.f), fmaxf(v0.w, 0.f),
                   fmaxf(v1.x, 0.f), fmaxf(v1.y, 0.f), fmaxf(v1.z, 0.f), fmaxf(v1.w, 0.f)};
    __nv_bfloat16 h[8], l[8];
#pragma unroll
    for (int j = 0; j < 8; j++) {
        __nv_bfloat16 hh = __float2bfloat16_rn(vv[j]);
        h[j] = hh;
        l[j] = __float2bfloat16_rn(vv[j] - __bfloat162float(hh));
    }
    __nv_bfloat16* o = Xs + (size_t)row * 128 + seg * 8;
    *(uint4*)o        = *(uint4*)h;
    *(uint4*)(o + 64) = *(uint4*)l;
}

// ---------------------------------------------------------------- edge kernel (cp.async gather, packed records)
__global__ void __launch_bounds__(256, 3) k_edges(const __nv_bfloat16* __restrict__ Xs,
                                                  const __nv_bfloat16* __restrict__ Ws,
                                                  float* __restrict__ O) {
    int t = blockIdx.x;
    if (t >= g_numTiles) return;
    int r  = g_tileRel[t];
    int s0 = g_tileStart[t];
    int m  = min(g_relOff[r + 1] - s0, TILE);

    extern __shared__ char smem[];
    uint32_t sb = smem_u32(smem);
    int*   sDst  = (int*)(smem + SM_DST);
    float* sNorm = (float*)(smem + SM_NRM);
    int tid = threadIdx.x;

    // ---- B tile via cp.async (4 x 16B per thread) ----
    {
        int n = tid >> 2, c = tid & 3;
        const char* wr = (const char*)(Ws + ((size_t)(r * DIM + n) * 128 + (c & 1) * 32 + (c >> 1) * 64));
        uint32_t db = sb + ((c >> 1) ? SM_BL : SM_BH) + n * 144 + (c & 1) * 64;
#pragma unroll
        for (int j = 0; j < 4; j++) CP16(db + j * 16, wr + j * 16);
    }
    // ---- A gather via cp.async (2 threads per row, packed record) ----
    {
        int e = tid >> 1, half = tid & 1;
        uint32_t ah = sb + SM_AH + e * 144 + half * 64;
        uint32_t al = sb + SM_AL + e * 144 + half * 64;
        if (e < m) {
            int4 rec = g_edgeP[s0 + e];
            int sr = rec.x;
            if (half == 0) { sDst[e] = rec.y; sNorm[e] = __int_as_float(rec.z); }
            const char* xr = (const char*)(Xs + (size_t)sr * 128) + half * 64;
#pragma unroll
            for (int j = 0; j < 4; j++) CP16(ah + j * 16, xr + j * 16);
#pragma unroll
            for (int j = 0; j < 4; j++) CP16(al + j * 16, xr + 128 + j * 16);
        } else {
            uint4 z = make_uint4(0, 0, 0, 0);
#pragma unroll
            for (int j = 0; j < 4; j++) {
                *(uint4*)(smem + SM_AH + e * 144 + half * 64 + j * 16) = z;
                *(uint4*)(smem + SM_AL + e * 144 + half * 64 + j * 16) = z;
            }
        }
    }
    CP_COMMIT();
    CP_WAIT0();
    __syncthreads();

    int lane = tid & 31, wid = tid >> 5;
    int g = lane >> 2, tg = lane & 3;
    int m0 = wid * 16;

    float c[8][4];
#pragma unroll
    for (int n = 0; n < 8; n++) { c[n][0] = 0.f; c[n][1] = 0.f; c[n][2] = 0.f; c[n][3] = 0.f; }

#pragma unroll
    for (int ks = 0; ks < 4; ks++) {
        int k0 = ks * 16;
        uint32_t ah[4], al[4];
        {
            const char* pLo = smem + SM_AH + ((m0 + g) * SAK + k0 + 2 * tg) * 2;
            const char* pHi = pLo + 8 * SAK * 2;
            ah[0] = *(const uint32_t*)pLo;  ah[1] = *(const uint32_t*)pHi;
            ah[2] = *(const uint32_t*)(pLo + 16); ah[3] = *(const uint32_t*)(pHi + 16);
            const char* qLo = smem + SM_AL + ((m0 + g) * SAK + k0 + 2 * tg) * 2;
            const char* qHi = qLo + 8 * SAK * 2;
            al[0] = *(const uint32_t*)qLo;  al[1] = *(const uint32_t*)qHi;
            al[2] = *(const uint32_t*)(qLo + 16); al[3] = *(const uint32_t*)(qHi + 16);
        }
#pragma unroll
        for (int n = 0; n < 8; n++) {
            uint32_t off = (uint32_t)((n * 8 + g) * SBK + k0 + 2 * tg) * 2;
            uint32_t bh0 = *(const uint32_t*)(smem + SM_BH + off);
            uint32_t bh1 = *(const uint32_t*)(smem + SM_BH + off + 16);
            uint32_t bl0 = *(const uint32_t*)(smem + SM_BL + off);
            uint32_t bl1 = *(const uint32_t*)(smem + SM_BL + off + 16);
            MMA_BF16(c[n], ah, bh0, bh1);
            MMA_BF16(c[n], al, bh0, bh1);
            MMA_BF16(c[n], ah, bl0, bl1);
        }
    }

    // epilogue: norm, shfl-pair, red.global.add.v4
    int  col0 = (tg & 2) * 2;
    bool lead = (tg & 1) == 0;
    int rA = m0 + g, rB = rA + 8;
    int dA = (rA < m) ? sDst[rA] : -1;
    int dB = (rB < m) ? sDst[rB] : -1;
    float nA = (rA < m) ? sNorm[rA] : 0.f;
    float nB = (rB < m) ? sNorm[rB] : 0.f;
#pragma unroll
    for (int n = 0; n < 8; n++) {
        float x0 = c[n][0] * nA, y0 = c[n][1] * nA;
        float x1 = c[n][2] * nB, y1 = c[n][3] * nB;
        float qx0 = __shfl_xor_sync(0xffffffffu, x0, 1);
        float qy0 = __shfl_xor_sync(0xffffffffu, y0, 1);
        float qx1 = __shfl_xor_sync(0xffffffffu, x1, 1);
        float qy1 = __shfl_xor_sync(0xffffffffu, y1, 1);
        if (lead && dA >= 0)
            RED4(O + (size_t)dA * DIM + n * 8 + col0, x0, y0, qx0, qy0);
        if (lead && dB >= 0)
            RED4(O + (size_t)dB * DIM + n * 8 + col0, x1, y1, qx1, qy1);
    }
}

// ---------------------------------------------------------------- self-loop: O += X @ Wl (red.add; O pre-zeroed)
__global__ void __launch_bounds__(256, 3) k_selfloop(const __nv_bfloat16* __restrict__ Xs,
                                                     const __nv_bfloat16* __restrict__ Ws,
                                                     float* __restrict__ O) {
    int base = blockIdx.x * TILE;
    int m = min(TILE, NNODE - base);
    extern __shared__ char smem[];
    uint32_t sb = smem_u32(smem);
    int tid = threadIdx.x;

    {
        int n = tid >> 2, c = tid & 3;
        const char* wr = (const char*)(Ws + ((size_t)(NREL * DIM + n) * 128 + (c & 1) * 32 + (c >> 1) * 64));
        uint32_t db = sb + ((c >> 1) ? SM_BL : SM_BH) + n * 144 + (c & 1) * 64;
#pragma unroll
        for (int j = 0; j < 4; j++) CP16(db + j * 16, wr + j * 16);
    }
    {
        int e = tid >> 1, half = tid & 1;
        uint32_t ah = sb + SM_AH + e * 144 + half * 64;
        uint32_t al = sb + SM_AL + e * 144 + half * 64;
        if (e < m) {
            const char* xr = (const char*)(Xs + (size_t)(base + e) * 128) + half * 64;
#pragma unroll
            for (int j = 0; j < 4; j++) CP16(ah + j * 16, xr + j * 16);
#pragma unroll
            for (int j = 0; j < 4; j++) CP16(al + j * 16, xr + 128 + j * 16);
        } else {
            uint4 z = make_uint4(0, 0, 0, 0);
#pragma unroll
            for (int j = 0; j < 4; j++) {
                *(uint4*)(smem + SM_AH + e * 144 + half * 64 + j * 16) = z;
                *(uint4*)(smem + SM_AL + e * 144 + half * 64 + j * 16) = z;
            }
        }
    }
    CP_COMMIT();
    CP_WAIT0();
    __syncthreads();

    int lane = tid & 31, wid = tid >> 5;
    int g = lane >> 2, tg = lane & 3;
    int m0 = wid * 16;

    float c[8][4];
#pragma unroll
    for (int n = 0; n < 8; n++) { c[n][0] = 0.f; c[n][1] = 0.f; c[n][2] = 0.f; c[n][3] = 0.f; }

#pragma unroll
    for (int ks = 0; ks < 4; ks++) {
        int k0 = ks * 16;
        uint32_t ah[4], al[4];
        {
            const char* pLo = smem + SM_AH + ((m0 + g) * SAK + k0 + 2 * tg) * 2;
            const char* pHi = pLo + 8 * SAK * 2;
            ah[0] = *(const uint32_t*)pLo;  ah[1] = *(const uint32_t*)pHi;
            ah[2] = *(const uint32_t*)(pLo + 16); ah[3] = *(const uint32_t*)(pHi + 16);
            const char* qLo = smem + SM_AL + ((m0 + g) * SAK + k0 + 2 * tg) * 2;
            const char* qHi = qLo + 8 * SAK * 2;
            al[0] = *(const uint32_t*)qLo;  al[1] = *(const uint32_t*)qHi;
            al[2] = *(const uint32_t*)(qLo + 16); al[3] = *(const uint32_t*)(qHi + 16);
        }
#pragma unroll
        for (int n = 0; n < 8; n++) {
            uint32_t off = (uint32_t)((n * 8 + g) * SBK + k0 + 2 * tg) * 2;
            uint32_t bh0 = *(const uint32_t*)(smem + SM_BH + off);
            uint32_t bh1 = *(const uint32_t*)(smem + SM_BH + off + 16);
            uint32_t bl0 = *(const uint32_t*)(smem + SM_BL + off);
            uint32_t bl1 = *(const uint32_t*)(smem + SM_BL + off + 16);
            MMA_BF16(c[n], ah, bh0, bh1);
            MMA_BF16(c[n], al, bh0, bh1);
            MMA_BF16(c[n], ah, bl0, bl1);
        }
    }

    int  col0 = (tg & 2) * 2;
    bool lead = (tg & 1) == 0;
    int rA = m0 + g, rB = rA + 8;
    bool okA = rA < m, okB = rB < m;
#pragma unroll
    for (int n = 0; n < 8; n++) {
        float x0 = c[n][0], y0 = c[n][1];
        float x1 = c[n][2], y1 = c[n][3];
        float qx0 = __shfl_xor_sync(0xffffffffu, x0, 1);
        float qy0 = __shfl_xor_sync(0xffffffffu, y0, 1);
        float qx1 = __shfl_xor_sync(0xffffffffu, x1, 1);
        float qy1 = __shfl_xor_sync(0xffffffffu, y1, 1);
        if (lead && okA)
            RED4(O + (size_t)(base + rA) * DIM + n * 8 + col0, x0, y0, qx0, qy0);
        if (lead && okB)
            RED4(O + (size_t)(base + rB) * DIM + n * 8 + col0, x1, y1, qx1, qy1);
    }
}

// ---------------------------------------------------------------- relu (final)
__global__ void k_relu(float* __restrict__ O, int n4) {
    int i = blockIdx.x * blockDim.x + threadIdx.x;
    if (i < n4) {
        float4 v = ((float4*)O)[i];
        v.x = fmaxf(v.x, 0.f); v.y = fmaxf(v.y, 0.f);
        v.z = fmaxf(v.z, 0.f); v.w = fmaxf(v.w, 0.f);
        ((float4*)O)[i] = v;
    }
}

// ---------------------------------------------------------------- launch
extern "C" void kernel_launch(void* const* d_in, const int* in_sizes, int n_in,
                              void* d_out, int out_size) {
    const float* x   = (const float*)d_in[0];
    const int*   src = (const int*)d_in[1];
    const int*   dst = (const int*)d_in[2];
    const int*   et  = (const int*)d_in[3];
    const float* W1  = (const float*)d_in[4];
    const float* Wl1 = (const float*)d_in[5];
    const float* W2  = (const float*)d_in[6];
    const float* Wl2 = (const float*)d_in[7];
    float* out = (float*)d_out;

    void* p;
    cudaGetSymbolAddress(&p, g_h);   float* h  = (float*)p;
    cudaGetSymbolAddress(&p, g_Xs);  __nv_bfloat16* Xs = (__nv_bfloat16*)p;
    cudaGetSymbolAddress(&p, g_Hs);  __nv_bfloat16* Hs = (__nv_bfloat16*)p;
    cudaGetSymbolAddress(&p, g_Ws1); __nv_bfloat16* Ws1 = (__nv_bfloat16*)p;
    cudaGetSymbolAddress(&p, g_Ws2); __nv_bfloat16* Ws2 = (__nv_bfloat16*)p;
    void* cntp;
    cudaGetSymbolAddress(&cntp, g_cnt);

    cudaFuncSetAttribute(k_edges,    cudaFuncAttributeMaxDynamicSharedMemorySize, SM_TOT);
    cudaFuncSetAttribute(k_selfloop, cudaFuncAttributeMaxDynamicSharedMemorySize, SM_TOT);

    const int TPB = 256;
    int nBlocksRows = (NNODE + TILE - 1) / TILE;
    int n4 = NNODE * DIM / 4;

    cudaStream_t s1;
    cudaStreamCreateWithFlags(&s1, cudaStreamNonBlocking);
    cudaEvent_t e0, e_xs, e_sl1, e_rs, e_sl2;
    cudaEventCreateWithFlags(&e0,   cudaEventDisableTiming);
    cudaEventCreateWithFlags(&e_xs, cudaEventDisableTiming);
    cudaEventCreateWithFlags(&e_sl1, cudaEventDisableTiming);
    cudaEventCreateWithFlags(&e_rs,  cudaEventDisableTiming);
    cudaEventCreateWithFlags(&e_sl2, cudaEventDisableTiming);

    // only the cnt memset gates branch A; fork immediately
    cudaMemsetAsync(cntp, 0, (size_t)NNODE * NREL * sizeof(int));
    cudaEventRecord(e0, 0);
    cudaStreamWaitEvent(s1, e0, 0);

    // branch A (main): counting-sort preprocessing
    k_hist<<<NB, TPB>>>(dst, et);
    k_scanRel<<<NREL, 128>>>();
    k_scanTiles<<<1, 128>>>();
    k_scatter<<<NB, TPB>>>(src, dst, et);

    // branch B (side): output zeroing + splits + layer-1 self-loop (red into h)
    cudaMemsetAsync(h,   0, (size_t)NNODE * DIM * sizeof(float), s1);
    cudaMemsetAsync(out, 0, (size_t)NNODE * DIM * sizeof(float), s1);
    k_wsplit<<<2 * (NREL + 1), 256, 0, s1>>>(W1, Wl1, W2, Wl2, Ws1, Ws2);
    k_xsplit<<<(NNODE * 8 + 255) / 256, 256, 0, s1>>>(x, Xs);
    cudaEventRecord(e_xs, s1);
    k_selfloop<<<nBlocksRows, TPB, SM_TOT, s1>>>(Xs, Ws1, h);
    cudaEventRecord(e_sl1, s1);

    // edges1 needs sort (main order) + Xs + zeroed h (e_xs); NOT selfloop1
    cudaStreamWaitEvent(0, e_xs, 0);
    k_edges<<<NTILES_MAX, TPB, SM_TOT>>>(Xs, Ws1, h);

    // relu_split needs edges1 (main) + selfloop1 (side)
    cudaStreamWaitEvent(0, e_sl1, 0);
    k_relu_split<<<(NNODE * 8 + 255) / 256, 256>>>(h, Hs);

    // layer 2: selfloop (side) and edges (main) reduce concurrently into zeroed out
    cudaEventRecord(e_rs, 0);
    cudaStreamWaitEvent(s1, e_rs, 0);
    k_selfloop<<<nBlocksRows, TPB, SM_TOT, s1>>>(Hs, Ws2, out);
    cudaEventRecord(e_sl2, s1);
    k_edges<<<NTILES_MAX, TPB, SM_TOT>>>(Hs, Ws2, out);
    cudaStreamWaitEvent(0, e_sl2, 0);

    k_relu<<<(n4 + TPB - 1) / TPB, TPB>>>(out, n4);

    cudaEventDestroy(e0);
    cudaEventDestroy(e_xs);
    cudaEventDestroy(e_sl1);
    cudaEventDestroy(e_rs);
    cudaEventDestroy(e_sl2);
    cudaStreamDestroy(s1);
}